// round 7
// baseline (speedup 1.0000x reference)
#include <cuda_runtime.h>
#include <cuda_fp16.h>
#include <math.h>
#include <stdint.h>

#define T_ 8192
#define D_ 1024
#define H_ 4096
#define E_ 8

#define BM 128
#define BN 256
#define BK 64
#define NT 256
#define STAGES 3
#define TILE_A_B (128 * 128)             // 128x64 fp16 A tile = 16384 bytes
#define TILE_B_B (256 * 128)             // 256x64 fp16 B tile = 32768 bytes
#define STAGE_B (TILE_A_B + TILE_B_B)    // 49152
#define SMEM_DYN (STAGES * STAGE_B)      // 147456

// ---------------- static device scratch ----------------
__device__ float g_gs[E_];
__device__ int   g_cnt[E_];
__device__ int   g_assign[T_ * 2];
__device__ __half g_xg[(size_t)E_ * T_ * D_];
__device__ __half g_w1[(size_t)E_ * H_ * D_];
__device__ __half g_w2[(size_t)E_ * D_ * H_];
__device__ __half g_h[(size_t)E_ * T_ * H_];
__device__ float g_partial[(size_t)E_ * T_ * D_];

// ---------------- PTX helpers (generic sm_103-legal) ----------------
__device__ __forceinline__ uint32_t s2u(const void* p) {
    uint32_t a;
    asm("{ .reg .u64 t; cvta.to.shared.u64 t, %1; cvt.u32.u64 %0, t; }" : "=r"(a) : "l"(p));
    return a;
}
__device__ __forceinline__ void cpa16(uint32_t dst, const void* src) {
    asm volatile("cp.async.cg.shared.global [%0], [%1], 16;\n" :: "r"(dst), "l"(src) : "memory");
}
__device__ __forceinline__ void cpa_commit() { asm volatile("cp.async.commit_group;\n" ::: "memory"); }
template <int N> __device__ __forceinline__ void cpa_wait() {
    asm volatile("cp.async.wait_group %0;\n" :: "n"(N) : "memory");
}
__device__ __forceinline__ void ldsm_x4(uint32_t a, uint32_t& r0, uint32_t& r1, uint32_t& r2, uint32_t& r3) {
    asm volatile("ldmatrix.sync.aligned.m8n8.x4.shared.b16 {%0,%1,%2,%3}, [%4];"
                 : "=r"(r0), "=r"(r1), "=r"(r2), "=r"(r3) : "r"(a));
}
__device__ __forceinline__ void mma_f16(float* d, const uint32_t* a, const uint32_t* b) {
    asm volatile("mma.sync.aligned.m16n8k16.row.col.f32.f16.f16.f32 "
                 "{%0,%1,%2,%3}, {%4,%5,%6,%7}, {%8,%9}, {%0,%1,%2,%3};"
                 : "+f"(d[0]), "+f"(d[1]), "+f"(d[2]), "+f"(d[3])
                 : "r"(a[0]), "r"(a[1]), "r"(a[2]), "r"(a[3]), "r"(b[0]), "r"(b[1]));
}
// swizzled byte offset inside a Nx64 fp16 tile (rows of 128B, 16B chunks)
__device__ __forceinline__ uint32_t sw_off(int r, int c) {
    return (uint32_t)(r * 128 + ((c ^ (r & 7)) << 4));
}

// ---------------- small kernels ----------------
__global__ void zero_counts_kernel() {
    if (threadIdx.x < E_) g_cnt[threadIdx.x] = 0;
}

__global__ void gate_norm_kernel(const float* __restrict__ gv, const float* __restrict__ gg) {
    int row = threadIdx.x >> 5;
    if (row >= E_) return;
    int lane = threadIdx.x & 31;
    const float4* p = (const float4*)(gv + (size_t)row * D_);
    float s = 0.f;
    for (int i = lane; i < D_ / 4; i += 32) {
        float4 a = p[i];
        s += a.x * a.x + a.y * a.y + a.z * a.z + a.w * a.w;
    }
    #pragma unroll
    for (int o = 16; o; o >>= 1) s += __shfl_xor_sync(0xffffffffu, s, o);
    if (lane == 0) g_gs[row] = gg[row] / fmaxf(sqrtf(s), 1e-12f);
}

// one warp per token: 8 gate logits, top-2, compact into expert slot lists
__global__ void route_kernel(const float* __restrict__ x,
                             const float* __restrict__ gate_v,
                             const float* __restrict__ gate_b)
{
    int t = (blockIdx.x * blockDim.x + threadIdx.x) >> 5;
    if (t >= T_) return;
    int lane = threadIdx.x & 31;
    const float4* xp = (const float4*)(x + (size_t)t * D_);
    float4 xr[8];
    #pragma unroll
    for (int i = 0; i < 8; i++) xr[i] = xp[lane + 32 * i];
    float logit[E_];
    #pragma unroll
    for (int e = 0; e < E_; e++) {
        const float4* gp = (const float4*)(gate_v + (size_t)e * D_);
        float s = 0.f;
        #pragma unroll
        for (int i = 0; i < 8; i++) {
            float4 g4 = gp[lane + 32 * i];
            s += xr[i].x * g4.x + xr[i].y * g4.y + xr[i].z * g4.z + xr[i].w * g4.w;
        }
        #pragma unroll
        for (int o = 16; o; o >>= 1) s += __shfl_xor_sync(0xffffffffu, s, o);
        logit[e] = s;
    }
    if (lane == 0) {
        int b0 = -1, b1i = -1;
        float v0 = -1e30f, v1 = -1e30f;
        #pragma unroll
        for (int e = 0; e < E_; e++) {
            float l = logit[e] * g_gs[e] + gate_b[e];
            if (l > v0)      { v1 = v0; b1i = b0; v0 = l; b0 = e; }
            else if (l > v1) { v1 = l; b1i = e; }
        }
        int e0 = min(b0, b1i), e1 = max(b0, b1i);
        int s0 = atomicAdd(&g_cnt[e0], 1);
        g_assign[2 * t] = e0 * T_ + s0;
        int s1 = atomicAdd(&g_cnt[e1], 1);
        g_assign[2 * t + 1] = e1 * T_ + s1;
    }
}

// gather x rows into assignment slots as fp16
__global__ void gather_kernel(const float* __restrict__ x) {
    int t = blockIdx.x;
    int i = threadIdx.x;   // 256 threads * float4 = 1024
    float4 v = ((const float4*)(x + (size_t)t * D_))[i];
    unsigned short h[4];
    h[0] = __half_as_ushort(__float2half_rn(v.x));
    h[1] = __half_as_ushort(__float2half_rn(v.y));
    h[2] = __half_as_ushort(__float2half_rn(v.z));
    h[3] = __half_as_ushort(__float2half_rn(v.w));
    uint2 hp;
    hp.x = (uint32_t)h[0] | ((uint32_t)h[1] << 16);
    hp.y = (uint32_t)h[2] | ((uint32_t)h[3] << 16);
    int a0 = g_assign[2 * t], a1 = g_assign[2 * t + 1];
    ((uint2*)(g_xg + (size_t)a0 * D_))[i] = hp;
    ((uint2*)(g_xg + (size_t)a1 * D_))[i] = hp;
}

// fused weight-norm + scale-fold + fp16 quantize. which=0 -> w1, 1 -> w2
__global__ void wconv_kernel(const float* __restrict__ v, const float* __restrict__ g,
                             int which, int K)
{
    int row = (blockIdx.x * blockDim.x + threadIdx.x) >> 5;
    int lane = threadIdx.x & 31;
    const float4* p = (const float4*)(v + (size_t)row * K);
    float s = 0.f;
    int n4 = K >> 2;
    for (int i = lane; i < n4; i += 32) {
        float4 a = p[i];
        s += a.x * a.x + a.y * a.y + a.z * a.z + a.w * a.w;
    }
    #pragma unroll
    for (int o = 16; o; o >>= 1) s += __shfl_xor_sync(0xffffffffu, s, o);
    float scl = g[row] / fmaxf(sqrtf(s), 1e-12f);
    __half* whi = which ? g_w2 : g_w1;
    uint2* oh = (uint2*)(whi + (size_t)row * K);
    for (int i = lane; i < n4; i += 32) {
        float4 a = p[i];
        unsigned short h[4];
        h[0] = __half_as_ushort(__float2half_rn(a.x * scl));
        h[1] = __half_as_ushort(__float2half_rn(a.y * scl));
        h[2] = __half_as_ushort(__float2half_rn(a.z * scl));
        h[3] = __half_as_ushort(__float2half_rn(a.w * scl));
        uint2 hp;
        hp.x = (uint32_t)h[0] | ((uint32_t)h[1] << 16);
        hp.y = (uint32_t)h[2] | ((uint32_t)h[3] << 16);
        oh[i] = hp;
    }
}

// ---------------- fp16 HMMA GEMM (mma.sync m16n8k16, CTA 128x256, warp 64x64) ----------------
// FIRST: [cnt,1024] @ w1^T -> swish -> g_h (fp16)
// else : [cnt,4096] @ w2^T -> + b2  -> g_partial (fp32)
template <int K, bool FIRST>
__global__ __launch_bounds__(NT, 1) void gemm_kernel(const float* __restrict__ bias)
{
    const int e   = blockIdx.z;
    const int cnt = g_cnt[e];
    const int m0  = blockIdx.y * BM;
    if (m0 >= cnt) return;
    const int n0  = blockIdx.x * BN;
    constexpr int NTOT = FIRST ? H_ : D_;
    constexpr int NC = K / BK;

    extern __shared__ char smem_raw[];
    const uint32_t sbase = s2u(smem_raw);
    const int tid  = threadIdx.x;
    const int lane = tid & 31;
    const int wid  = tid >> 5;
    const int wm   = (wid & 1) * 64;   // warp m offset in tile
    const int wn   = (wid >> 1) * 64;  // warp n offset in tile (4 x 64 = 256)

    const size_t arow = (size_t)(e * T_ + m0);
    const __half* A_g = (FIRST ? g_xg : g_h) + arow * K;
    const __half* B_g = (FIRST ? g_w1 : g_w2) + ((size_t)e * NTOT + n0) * K;

    auto load_chunk = [&](int c, int s) {
        uint32_t stg = sbase + s * STAGE_B;
        #pragma unroll
        for (int q = 0; q < 12; q++) {
            int i = tid + q * NT;          // 0..3071
            if (i < 1024) {                // A: 128 rows x 8 16B-chunks
                int r  = i >> 3;
                int cc = i & 7;
                cpa16(stg + sw_off(r, cc), A_g + (size_t)r * K + c * BK + cc * 8);
            } else {                       // B: 256 rows x 8 16B-chunks
                int j  = i - 1024;
                int r  = j >> 3;
                int cc = j & 7;
                cpa16(stg + TILE_A_B + sw_off(r, cc), B_g + (size_t)r * K + c * BK + cc * 8);
            }
        }
    };

    float acc[4][8][4] = {};

    // prologue: stage first STAGES-1 chunks
    #pragma unroll
    for (int c = 0; c < STAGES - 1; ++c) { load_chunk(c, c); cpa_commit(); }

    int s = 0;
    for (int c = 0; c < NC; ++c) {
        cpa_wait<STAGES - 2>();
        __syncthreads();
        const int cn = c + STAGES - 1;
        if (cn < NC) {
            int sn = s + STAGES - 1;
            if (sn >= STAGES) sn -= STAGES;
            load_chunk(cn, sn);
        }
        cpa_commit();

        const uint32_t sA = sbase + s * STAGE_B;
        const uint32_t sB = sA + TILE_A_B;

        #pragma unroll
        for (int ks = 0; ks < 4; ++ks) {
            uint32_t ah[4][4], bh[8][2];
            const int ar = lane & 15;
            const int ac = ks * 2 + (lane >> 4);
            #pragma unroll
            for (int im = 0; im < 4; im++) {
                uint32_t off = sw_off(wm + im * 16 + ar, ac);
                ldsm_x4(sA + off, ah[im][0], ah[im][1], ah[im][2], ah[im][3]);
            }
            // B: each ldmatrix.x4 covers 2 n-frags (16 rows) for this k16
            const int br = (lane & 7) + ((lane >> 4) << 3);
            const int bc = ks * 2 + ((lane >> 3) & 1);
            #pragma unroll
            for (int half = 0; half < 4; half++) {
                uint32_t off = sw_off(wn + half * 16 + br, bc);
                ldsm_x4(sB + off, bh[2 * half][0], bh[2 * half][1],
                                  bh[2 * half + 1][0], bh[2 * half + 1][1]);
            }
            #pragma unroll
            for (int im = 0; im < 4; im++)
                #pragma unroll
                for (int in = 0; in < 8; in++)
                    mma_f16(acc[im][in], ah[im], bh[in]);
        }
        if (++s == STAGES) s = 0;
    }

    // epilogue
    const int rbase = m0 + wm + (lane >> 2);
    #pragma unroll
    for (int im = 0; im < 4; im++) {
        #pragma unroll
        for (int half = 0; half < 2; half++) {
            const int mg = rbase + im * 16 + half * 8;
            if (mg >= cnt) continue;
            #pragma unroll
            for (int in = 0; in < 8; in++) {
                const int col = n0 + wn + in * 8 + 2 * (lane & 3);
                float z0 = acc[im][in][2 * half]     + bias[(size_t)e * NTOT + col];
                float z1 = acc[im][in][2 * half + 1] + bias[(size_t)e * NTOT + col + 1];
                if (FIRST) {
                    float w0 = z0 * __frcp_rn(1.f + __expf(-z0));
                    float w1 = z1 * __frcp_rn(1.f + __expf(-z1));
                    unsigned short h0 = __half_as_ushort(__float2half_rn(w0));
                    unsigned short h1 = __half_as_ushort(__float2half_rn(w1));
                    size_t o = ((size_t)(e * T_) + mg) * H_ + col;
                    *(uint32_t*)(g_h + o) = (uint32_t)h0 | ((uint32_t)h1 << 16);
                } else {
                    size_t o = ((size_t)(e * T_) + mg) * D_ + col;
                    *(float2*)(g_partial + o) = make_float2(z0, z1);
                }
            }
        }
    }
}

// out[t] = partial[a0] + partial[a1]
__global__ void sum_kernel(float* __restrict__ out) {
    int t = blockIdx.x;
    int a0 = g_assign[2 * t], a1 = g_assign[2 * t + 1];
    const float4* p0 = (const float4*)(g_partial + (size_t)a0 * D_);
    const float4* p1 = (const float4*)(g_partial + (size_t)a1 * D_);
    float4* o = (float4*)(out + (size_t)t * D_);
    int i = threadIdx.x;
    float4 u = p0[i], w = p1[i];
    o[i] = make_float4(u.x + w.x, u.y + w.y, u.z + w.z, u.w + w.w);
}

// ---------------- launch ----------------
extern "C" void kernel_launch(void* const* d_in, const int* in_sizes, int n_in,
                              void* d_out, int out_size)
{
    const float* x      = (const float*)d_in[0];
    const float* gate_v = (const float*)d_in[1];
    const float* gate_g = (const float*)d_in[2];
    const float* gate_b = (const float*)d_in[3];
    const float* w1_v   = (const float*)d_in[4];
    const float* w1_g   = (const float*)d_in[5];
    const float* b1     = (const float*)d_in[6];
    const float* w2_v   = (const float*)d_in[7];
    const float* w2_g   = (const float*)d_in[8];
    const float* b2     = (const float*)d_in[9];
    float* out = (float*)d_out;

    cudaFuncSetAttribute(gemm_kernel<D_, true>,  cudaFuncAttributeMaxDynamicSharedMemorySize, SMEM_DYN);
    cudaFuncSetAttribute(gemm_kernel<H_, false>, cudaFuncAttributeMaxDynamicSharedMemorySize, SMEM_DYN);

    zero_counts_kernel<<<1, 32>>>();
    gate_norm_kernel<<<1, 256>>>(gate_v, gate_g);
    route_kernel<<<T_ / 8, 256>>>(x, gate_v, gate_b);
    gather_kernel<<<T_, 256>>>(x);
    wconv_kernel<<<(E_ * H_) / 8, 256>>>(w1_v, w1_g, 0, D_);
    wconv_kernel<<<(E_ * D_) / 8, 256>>>(w2_v, w2_g, 1, H_);

    gemm_kernel<D_, true><<<dim3(H_ / BN, T_ / BM, E_), NT, SMEM_DYN>>>(b1);
    gemm_kernel<H_, false><<<dim3(D_ / BN, T_ / BM, E_), NT, SMEM_DYN>>>(b2);

    sum_kernel<<<T_, 256>>>(out);
}

// round 8
// speedup vs baseline: 1.1977x; 1.1977x over previous
#include <cuda_runtime.h>
#include <cuda_fp16.h>
#include <math.h>
#include <stdint.h>

#define T_ 8192
#define D_ 1024
#define H_ 4096
#define E_ 8

#define BM 128
#define BN 128
#define BK 64
#define NT 128
#define STAGES 3
#define TILE_B (128 * 128)           // one 128x64 fp16 tile = 16384 bytes
#define STAGE_B (2 * TILE_B)         // A, B = 32768
#define SMEM_DYN (STAGES * STAGE_B)  // 98304

// ---------------- static device scratch ----------------
__device__ float g_gs[E_];
__device__ int   g_cnt[E_];
__device__ int   g_assign[T_ * 2];
__device__ __half g_xg[(size_t)E_ * T_ * D_];
__device__ __half g_w1[(size_t)E_ * H_ * D_];
__device__ __half g_w2[(size_t)E_ * D_ * H_];
__device__ __half g_h[(size_t)E_ * T_ * H_];
__device__ float g_partial[(size_t)E_ * T_ * D_];

// ---------------- PTX helpers (generic sm_103-legal) ----------------
__device__ __forceinline__ uint32_t s2u(const void* p) {
    uint32_t a;
    asm("{ .reg .u64 t; cvta.to.shared.u64 t, %1; cvt.u32.u64 %0, t; }" : "=r"(a) : "l"(p));
    return a;
}
__device__ __forceinline__ void cpa16(uint32_t dst, const void* src) {
    asm volatile("cp.async.cg.shared.global [%0], [%1], 16;\n" :: "r"(dst), "l"(src) : "memory");
}
__device__ __forceinline__ void cpa_commit() { asm volatile("cp.async.commit_group;\n" ::: "memory"); }
template <int N> __device__ __forceinline__ void cpa_wait() {
    asm volatile("cp.async.wait_group %0;\n" :: "n"(N) : "memory");
}
__device__ __forceinline__ void ldsm_x4(uint32_t a, uint32_t& r0, uint32_t& r1, uint32_t& r2, uint32_t& r3) {
    asm volatile("ldmatrix.sync.aligned.m8n8.x4.shared.b16 {%0,%1,%2,%3}, [%4];"
                 : "=r"(r0), "=r"(r1), "=r"(r2), "=r"(r3) : "r"(a));
}
__device__ __forceinline__ void mma_f16(float* d, const uint32_t* a, const uint32_t* b) {
    asm volatile("mma.sync.aligned.m16n8k16.row.col.f32.f16.f16.f32 "
                 "{%0,%1,%2,%3}, {%4,%5,%6,%7}, {%8,%9}, {%0,%1,%2,%3};"
                 : "+f"(d[0]), "+f"(d[1]), "+f"(d[2]), "+f"(d[3])
                 : "r"(a[0]), "r"(a[1]), "r"(a[2]), "r"(a[3]), "r"(b[0]), "r"(b[1]));
}
// swizzled byte offset inside a Nx64 fp16 tile (rows of 128B, 16B chunks)
__device__ __forceinline__ uint32_t sw_off(int r, int c) {
    return (uint32_t)(r * 128 + ((c ^ (r & 7)) << 4));
}

// ---------------- small kernels ----------------
__global__ void zero_counts_kernel() {
    if (threadIdx.x < E_) g_cnt[threadIdx.x] = 0;
}

__global__ void gate_norm_kernel(const float* __restrict__ gv, const float* __restrict__ gg) {
    int row = threadIdx.x >> 5;
    if (row >= E_) return;
    int lane = threadIdx.x & 31;
    const float4* p = (const float4*)(gv + (size_t)row * D_);
    float s = 0.f;
    for (int i = lane; i < D_ / 4; i += 32) {
        float4 a = p[i];
        s += a.x * a.x + a.y * a.y + a.z * a.z + a.w * a.w;
    }
    #pragma unroll
    for (int o = 16; o; o >>= 1) s += __shfl_xor_sync(0xffffffffu, s, o);
    if (lane == 0) g_gs[row] = gg[row] / fmaxf(sqrtf(s), 1e-12f);
}

// one warp per token: 8 gate logits, top-2, compact into expert slot lists
__global__ void route_kernel(const float* __restrict__ x,
                             const float* __restrict__ gate_v,
                             const float* __restrict__ gate_b)
{
    int t = (blockIdx.x * blockDim.x + threadIdx.x) >> 5;
    if (t >= T_) return;
    int lane = threadIdx.x & 31;
    const float4* xp = (const float4*)(x + (size_t)t * D_);
    float4 xr[8];
    #pragma unroll
    for (int i = 0; i < 8; i++) xr[i] = xp[lane + 32 * i];
    float logit[E_];
    #pragma unroll
    for (int e = 0; e < E_; e++) {
        const float4* gp = (const float4*)(gate_v + (size_t)e * D_);
        float s = 0.f;
        #pragma unroll
        for (int i = 0; i < 8; i++) {
            float4 g4 = gp[lane + 32 * i];
            s += xr[i].x * g4.x + xr[i].y * g4.y + xr[i].z * g4.z + xr[i].w * g4.w;
        }
        #pragma unroll
        for (int o = 16; o; o >>= 1) s += __shfl_xor_sync(0xffffffffu, s, o);
        logit[e] = s;
    }
    if (lane == 0) {
        int b0 = -1, b1i = -1;
        float v0 = -1e30f, v1 = -1e30f;
        #pragma unroll
        for (int e = 0; e < E_; e++) {
            float l = logit[e] * g_gs[e] + gate_b[e];
            if (l > v0)      { v1 = v0; b1i = b0; v0 = l; b0 = e; }
            else if (l > v1) { v1 = l; b1i = e; }
        }
        int e0 = min(b0, b1i), e1 = max(b0, b1i);
        int s0 = atomicAdd(&g_cnt[e0], 1);
        g_assign[2 * t] = e0 * T_ + s0;
        int s1 = atomicAdd(&g_cnt[e1], 1);
        g_assign[2 * t + 1] = e1 * T_ + s1;
    }
}

// gather x rows into assignment slots as fp16
__global__ void gather_kernel(const float* __restrict__ x) {
    int t = blockIdx.x;
    int i = threadIdx.x;   // 256 threads * float4 = 1024
    float4 v = ((const float4*)(x + (size_t)t * D_))[i];
    unsigned short h[4];
    h[0] = __half_as_ushort(__float2half_rn(v.x));
    h[1] = __half_as_ushort(__float2half_rn(v.y));
    h[2] = __half_as_ushort(__float2half_rn(v.z));
    h[3] = __half_as_ushort(__float2half_rn(v.w));
    uint2 hp;
    hp.x = (uint32_t)h[0] | ((uint32_t)h[1] << 16);
    hp.y = (uint32_t)h[2] | ((uint32_t)h[3] << 16);
    int a0 = g_assign[2 * t], a1 = g_assign[2 * t + 1];
    ((uint2*)(g_xg + (size_t)a0 * D_))[i] = hp;
    ((uint2*)(g_xg + (size_t)a1 * D_))[i] = hp;
}

// fused weight-norm + scale-fold + fp16 quantize. which=0 -> w1, 1 -> w2
__global__ void wconv_kernel(const float* __restrict__ v, const float* __restrict__ g,
                             int which, int K)
{
    int row = (blockIdx.x * blockDim.x + threadIdx.x) >> 5;
    int lane = threadIdx.x & 31;
    const float4* p = (const float4*)(v + (size_t)row * K);
    float s = 0.f;
    int n4 = K >> 2;
    for (int i = lane; i < n4; i += 32) {
        float4 a = p[i];
        s += a.x * a.x + a.y * a.y + a.z * a.z + a.w * a.w;
    }
    #pragma unroll
    for (int o = 16; o; o >>= 1) s += __shfl_xor_sync(0xffffffffu, s, o);
    float scl = g[row] / fmaxf(sqrtf(s), 1e-12f);
    __half* whi = which ? g_w2 : g_w1;
    uint2* oh = (uint2*)(whi + (size_t)row * K);
    for (int i = lane; i < n4; i += 32) {
        float4 a = p[i];
        unsigned short h[4];
        h[0] = __half_as_ushort(__float2half_rn(a.x * scl));
        h[1] = __half_as_ushort(__float2half_rn(a.y * scl));
        h[2] = __half_as_ushort(__float2half_rn(a.z * scl));
        h[3] = __half_as_ushort(__float2half_rn(a.w * scl));
        uint2 hp;
        hp.x = (uint32_t)h[0] | ((uint32_t)h[1] << 16);
        hp.y = (uint32_t)h[2] | ((uint32_t)h[3] << 16);
        oh[i] = hp;
    }
}

// ---------------- fp16 HMMA GEMM (mma.sync m16n8k16, CTA 128x128, 4 warps of 64x64) ----------------
// FIRST: [cnt,1024] @ w1^T -> swish -> g_h (fp16)
// else : [cnt,4096] @ w2^T -> + b2  -> g_partial (fp32)
template <int K, bool FIRST>
__global__ __launch_bounds__(NT, 2) void gemm_kernel(const float* __restrict__ bias)
{
    const int e   = blockIdx.z;
    const int cnt = g_cnt[e];
    const int m0  = blockIdx.y * BM;
    if (m0 >= cnt) return;
    const int n0  = blockIdx.x * BN;
    constexpr int NTOT = FIRST ? H_ : D_;
    constexpr int NC = K / BK;

    extern __shared__ char smem_raw[];
    const uint32_t sbase = s2u(smem_raw);
    const int tid  = threadIdx.x;
    const int lane = tid & 31;
    const int wid  = tid >> 5;
    const int wm   = (wid & 1) * 64;   // warp m offset in tile
    const int wn   = (wid >> 1) * 64;  // warp n offset in tile (2 x 64 = 128)

    const size_t arow = (size_t)(e * T_ + m0);
    const __half* A_g = (FIRST ? g_xg : g_h) + arow * K;
    const __half* B_g = (FIRST ? g_w1 : g_w2) + ((size_t)e * NTOT + n0) * K;

    auto load_chunk = [&](int c, int s) {
        uint32_t stg = sbase + s * STAGE_B;
        #pragma unroll
        for (int q = 0; q < 16; q++) {
            int i   = tid + q * NT;       // 0..2047
            int mtx = i >> 10;            // 0 A, 1 B
            int rem = i & 1023;
            int r   = rem >> 3;
            int cc  = rem & 7;
            const __half* src = (mtx == 0) ? A_g : B_g;
            src += (size_t)r * K + c * BK + cc * 8;
            cpa16(stg + mtx * TILE_B + sw_off(r, cc), src);
        }
    };

    float acc[4][8][4] = {};

    // prologue: stage first STAGES-1 chunks
    #pragma unroll
    for (int c = 0; c < STAGES - 1; ++c) { load_chunk(c, c); cpa_commit(); }

    int s = 0;
    for (int c = 0; c < NC; ++c) {
        cpa_wait<STAGES - 2>();
        __syncthreads();
        const int cn = c + STAGES - 1;
        if (cn < NC) {
            int sn = s + STAGES - 1;
            if (sn >= STAGES) sn -= STAGES;
            load_chunk(cn, sn);
        }
        cpa_commit();

        const uint32_t sA = sbase + s * STAGE_B;
        const uint32_t sB = sA + TILE_B;

        #pragma unroll
        for (int ks = 0; ks < 4; ++ks) {
            uint32_t ah[4][4], bh[8][2];
            const int ar = lane & 15;
            const int ac = ks * 2 + (lane >> 4);
            #pragma unroll
            for (int im = 0; im < 4; im++) {
                uint32_t off = sw_off(wm + im * 16 + ar, ac);
                ldsm_x4(sA + off, ah[im][0], ah[im][1], ah[im][2], ah[im][3]);
            }
            // B: each ldmatrix.x4 covers 2 n-frags (16 rows) for this k16
            const int br = (lane & 7) + ((lane >> 4) << 3);
            const int bc = ks * 2 + ((lane >> 3) & 1);
            #pragma unroll
            for (int half = 0; half < 4; half++) {
                uint32_t off = sw_off(wn + half * 16 + br, bc);
                ldsm_x4(sB + off, bh[2 * half][0], bh[2 * half][1],
                                  bh[2 * half + 1][0], bh[2 * half + 1][1]);
            }
            #pragma unroll
            for (int im = 0; im < 4; im++)
                #pragma unroll
                for (int in = 0; in < 8; in++)
                    mma_f16(acc[im][in], ah[im], bh[in]);
        }
        if (++s == STAGES) s = 0;
    }

    // epilogue
    const int rbase = m0 + wm + (lane >> 2);
    #pragma unroll
    for (int im = 0; im < 4; im++) {
        #pragma unroll
        for (int half = 0; half < 2; half++) {
            const int mg = rbase + im * 16 + half * 8;
            if (mg >= cnt) continue;
            #pragma unroll
            for (int in = 0; in < 8; in++) {
                const int col = n0 + wn + in * 8 + 2 * (lane & 3);
                float z0 = acc[im][in][2 * half]     + bias[(size_t)e * NTOT + col];
                float z1 = acc[im][in][2 * half + 1] + bias[(size_t)e * NTOT + col + 1];
                if (FIRST) {
                    float w0 = z0 * __frcp_rn(1.f + __expf(-z0));
                    float w1 = z1 * __frcp_rn(1.f + __expf(-z1));
                    unsigned short h0 = __half_as_ushort(__float2half_rn(w0));
                    unsigned short h1 = __half_as_ushort(__float2half_rn(w1));
                    size_t o = ((size_t)(e * T_) + mg) * H_ + col;
                    *(uint32_t*)(g_h + o) = (uint32_t)h0 | ((uint32_t)h1 << 16);
                } else {
                    size_t o = ((size_t)(e * T_) + mg) * D_ + col;
                    *(float2*)(g_partial + o) = make_float2(z0, z1);
                }
            }
        }
    }
}

// out[t] = partial[a0] + partial[a1]
__global__ void sum_kernel(float* __restrict__ out) {
    int t = blockIdx.x;
    int a0 = g_assign[2 * t], a1 = g_assign[2 * t + 1];
    const float4* p0 = (const float4*)(g_partial + (size_t)a0 * D_);
    const float4* p1 = (const float4*)(g_partial + (size_t)a1 * D_);
    float4* o = (float4*)(out + (size_t)t * D_);
    int i = threadIdx.x;
    float4 u = p0[i], w = p1[i];
    o[i] = make_float4(u.x + w.x, u.y + w.y, u.z + w.z, u.w + w.w);
}

// ---------------- launch ----------------
extern "C" void kernel_launch(void* const* d_in, const int* in_sizes, int n_in,
                              void* d_out, int out_size)
{
    const float* x      = (const float*)d_in[0];
    const float* gate_v = (const float*)d_in[1];
    const float* gate_g = (const float*)d_in[2];
    const float* gate_b = (const float*)d_in[3];
    const float* w1_v   = (const float*)d_in[4];
    const float* w1_g   = (const float*)d_in[5];
    const float* b1     = (const float*)d_in[6];
    const float* w2_v   = (const float*)d_in[7];
    const float* w2_g   = (const float*)d_in[8];
    const float* b2     = (const float*)d_in[9];
    float* out = (float*)d_out;

    cudaFuncSetAttribute(gemm_kernel<D_, true>,  cudaFuncAttributeMaxDynamicSharedMemorySize, SMEM_DYN);
    cudaFuncSetAttribute(gemm_kernel<H_, false>, cudaFuncAttributeMaxDynamicSharedMemorySize, SMEM_DYN);

    zero_counts_kernel<<<1, 32>>>();
    gate_norm_kernel<<<1, 256>>>(gate_v, gate_g);
    route_kernel<<<T_ / 8, 256>>>(x, gate_v, gate_b);
    gather_kernel<<<T_, 256>>>(x);
    wconv_kernel<<<(E_ * H_) / 8, 256>>>(w1_v, w1_g, 0, D_);
    wconv_kernel<<<(E_ * D_) / 8, 256>>>(w2_v, w2_g, 1, H_);

    gemm_kernel<D_, true><<<dim3(H_ / BN, T_ / BM, E_), NT, SMEM_DYN>>>(b1);
    gemm_kernel<H_, false><<<dim3(D_ / BN, T_ / BM, E_), NT, SMEM_DYN>>>(b2);

    sum_kernel<<<T_, 256>>>(out);
}

// round 9
// speedup vs baseline: 1.2488x; 1.0427x over previous
#include <cuda_runtime.h>
#include <cuda_fp16.h>
#include <math.h>
#include <stdint.h>

#define T_ 8192
#define D_ 1024
#define H_ 4096
#define E_ 8

#define BM 128
#define BN 128
#define BK 64
#define NT 256
#define STAGES 3
#define TILE_B (128 * 128)           // one 128x64 fp16 tile = 16384 bytes
#define STAGE_B (2 * TILE_B)         // A, B = 32768
#define SMEM_DYN (STAGES * STAGE_B)  // 98304

// prep kernel block ranges
#define NB_ROUTE 1024                // 8 tokens/block
#define NB_CONV  2048                // 4 tokens/block
#define NB_W1    4096                // 8 rows/block (E*H = 32768 rows, K=1024)
#define NB_W2    1024                // 8 rows/block (E*D = 8192 rows,  K=4096)
#define NB_PREP  (NB_ROUTE + NB_CONV + NB_W1 + NB_W2)

// ---------------- static device scratch ----------------
__device__ float g_gs[E_];
__device__ int   g_cnt[E_];
__device__ int   g_tok[E_ * T_];          // expert slot -> token
__device__ int   g_assign[T_ * 2];        // token -> 2 assignment ids
__device__ __half g_x16[(size_t)T_ * D_]; // x in fp16 (single copy)
__device__ __half g_w1[(size_t)E_ * H_ * D_];
__device__ __half g_w2[(size_t)E_ * D_ * H_];
__device__ __half g_h[(size_t)E_ * T_ * H_];
__device__ float g_partial[(size_t)E_ * T_ * D_];

// ---------------- PTX helpers (generic sm_103-legal) ----------------
__device__ __forceinline__ uint32_t s2u(const void* p) {
    uint32_t a;
    asm("{ .reg .u64 t; cvta.to.shared.u64 t, %1; cvt.u32.u64 %0, t; }" : "=r"(a) : "l"(p));
    return a;
}
__device__ __forceinline__ void cpa16(uint32_t dst, const void* src) {
    asm volatile("cp.async.cg.shared.global [%0], [%1], 16;\n" :: "r"(dst), "l"(src) : "memory");
}
__device__ __forceinline__ void cpa_commit() { asm volatile("cp.async.commit_group;\n" ::: "memory"); }
template <int N> __device__ __forceinline__ void cpa_wait() {
    asm volatile("cp.async.wait_group %0;\n" :: "n"(N) : "memory");
}
__device__ __forceinline__ void ldsm_x4(uint32_t a, uint32_t& r0, uint32_t& r1, uint32_t& r2, uint32_t& r3) {
    asm volatile("ldmatrix.sync.aligned.m8n8.x4.shared.b16 {%0,%1,%2,%3}, [%4];"
                 : "=r"(r0), "=r"(r1), "=r"(r2), "=r"(r3) : "r"(a));
}
__device__ __forceinline__ void mma_f16(float* d, const uint32_t* a, const uint32_t* b) {
    asm volatile("mma.sync.aligned.m16n8k16.row.col.f32.f16.f16.f32 "
                 "{%0,%1,%2,%3}, {%4,%5,%6,%7}, {%8,%9}, {%0,%1,%2,%3};"
                 : "+f"(d[0]), "+f"(d[1]), "+f"(d[2]), "+f"(d[3])
                 : "r"(a[0]), "r"(a[1]), "r"(a[2]), "r"(a[3]), "r"(b[0]), "r"(b[1]));
}
// swizzled byte offset inside a Nx64 fp16 tile (rows of 128B, 16B chunks)
__device__ __forceinline__ uint32_t sw_off(int r, int c) {
    return (uint32_t)(r * 128 + ((c ^ (r & 7)) << 4));
}

// ---------------- init: zero counts + gate weight-norm scales ----------------
__global__ void init_kernel(const float* __restrict__ gv, const float* __restrict__ gg) {
    if (threadIdx.x < E_) g_cnt[threadIdx.x] = 0;
    int row = threadIdx.x >> 5;
    if (row >= E_) return;
    int lane = threadIdx.x & 31;
    const float4* p = (const float4*)(gv + (size_t)row * D_);
    float s = 0.f;
    for (int i = lane; i < D_ / 4; i += 32) {
        float4 a = p[i];
        s += a.x * a.x + a.y * a.y + a.z * a.z + a.w * a.w;
    }
    #pragma unroll
    for (int o = 16; o; o >>= 1) s += __shfl_xor_sync(0xffffffffu, s, o);
    if (lane == 0) g_gs[row] = gg[row] / fmaxf(sqrtf(s), 1e-12f);
}

// warp helper: weight-norm + fp16 quantize one row
__device__ __forceinline__ void wconv_row(const float* __restrict__ vrow, float gval,
                                          __half* __restrict__ orow, int K, int lane)
{
    const float4* p = (const float4*)vrow;
    float s = 0.f;
    int n4 = K >> 2;
    for (int i = lane; i < n4; i += 32) {
        float4 a = p[i];
        s += a.x * a.x + a.y * a.y + a.z * a.z + a.w * a.w;
    }
    #pragma unroll
    for (int o = 16; o; o >>= 1) s += __shfl_xor_sync(0xffffffffu, s, o);
    float scl = gval / fmaxf(sqrtf(s), 1e-12f);
    uint2* oh = (uint2*)orow;
    for (int i = lane; i < n4; i += 32) {
        float4 a = p[i];
        unsigned short h0 = __half_as_ushort(__float2half_rn(a.x * scl));
        unsigned short h1 = __half_as_ushort(__float2half_rn(a.y * scl));
        unsigned short h2 = __half_as_ushort(__float2half_rn(a.z * scl));
        unsigned short h3 = __half_as_ushort(__float2half_rn(a.w * scl));
        uint2 hp;
        hp.x = (uint32_t)h0 | ((uint32_t)h1 << 16);
        hp.y = (uint32_t)h2 | ((uint32_t)h3 << 16);
        oh[i] = hp;
    }
}

// ---------------- fused prep: route | x->fp16 convert | wconv(w1) | wconv(w2) ----------------
__global__ __launch_bounds__(256) void prep_kernel(
    const float* __restrict__ x,
    const float* __restrict__ gate_v, const float* __restrict__ gate_b,
    const float* __restrict__ w1_v, const float* __restrict__ w1_g,
    const float* __restrict__ w2_v, const float* __restrict__ w2_g)
{
    const int b = blockIdx.x;
    const int tid = threadIdx.x;
    const int lane = tid & 31;
    const int warp = tid >> 5;

    if (b < NB_ROUTE) {
        // ---- routing: 1 warp per token, 8 tokens/block ----
        int t = b * 8 + warp;
        const float4* xp = (const float4*)(x + (size_t)t * D_);
        float4 xr[8];
        #pragma unroll
        for (int i = 0; i < 8; i++) xr[i] = xp[lane + 32 * i];
        float logit[E_];
        #pragma unroll
        for (int e = 0; e < E_; e++) {
            const float4* gp = (const float4*)(gate_v + (size_t)e * D_);
            float s = 0.f;
            #pragma unroll
            for (int i = 0; i < 8; i++) {
                float4 g4 = gp[lane + 32 * i];
                s += xr[i].x * g4.x + xr[i].y * g4.y + xr[i].z * g4.z + xr[i].w * g4.w;
            }
            #pragma unroll
            for (int o = 16; o; o >>= 1) s += __shfl_xor_sync(0xffffffffu, s, o);
            logit[e] = s;
        }
        if (lane == 0) {
            int b0 = -1, b1i = -1;
            float v0 = -1e30f, v1 = -1e30f;
            #pragma unroll
            for (int e = 0; e < E_; e++) {
                float l = logit[e] * g_gs[e] + gate_b[e];
                if (l > v0)      { v1 = v0; b1i = b0; v0 = l; b0 = e; }
                else if (l > v1) { v1 = l; b1i = e; }
            }
            int e0 = min(b0, b1i), e1 = max(b0, b1i);
            int s0 = atomicAdd(&g_cnt[e0], 1);
            g_tok[e0 * T_ + s0] = t;
            g_assign[2 * t] = e0 * T_ + s0;
            int s1 = atomicAdd(&g_cnt[e1], 1);
            g_tok[e1 * T_ + s1] = t;
            g_assign[2 * t + 1] = e1 * T_ + s1;
        }
    } else if (b < NB_ROUTE + NB_CONV) {
        // ---- convert x -> fp16, 4 tokens/block ----
        int t0 = (b - NB_ROUTE) * 4;
        #pragma unroll
        for (int j = 0; j < 4; j++) {
            size_t base = (size_t)(t0 + j) * D_;
            float4 v = ((const float4*)(x + base))[tid];
            unsigned short h0 = __half_as_ushort(__float2half_rn(v.x));
            unsigned short h1 = __half_as_ushort(__float2half_rn(v.y));
            unsigned short h2 = __half_as_ushort(__float2half_rn(v.z));
            unsigned short h3 = __half_as_ushort(__float2half_rn(v.w));
            uint2 hp;
            hp.x = (uint32_t)h0 | ((uint32_t)h1 << 16);
            hp.y = (uint32_t)h2 | ((uint32_t)h3 << 16);
            ((uint2*)(g_x16 + base))[tid] = hp;
        }
    } else if (b < NB_ROUTE + NB_CONV + NB_W1) {
        // ---- w1 weight-norm+convert: 8 rows/block, K = D_ ----
        int row = (b - NB_ROUTE - NB_CONV) * 8 + warp;   // 0..E*H-1
        wconv_row(w1_v + (size_t)row * D_, w1_g[row], g_w1 + (size_t)row * D_, D_, lane);
    } else {
        // ---- w2 weight-norm+convert: 8 rows/block, K = H_ ----
        int row = (b - NB_ROUTE - NB_CONV - NB_W1) * 8 + warp;   // 0..E*D-1
        wconv_row(w2_v + (size_t)row * H_, w2_g[row], g_w2 + (size_t)row * H_, H_, lane);
    }
}

// ---------------- fp16 HMMA GEMM (r6 config: CTA 128x128, 8 warps of 64x32, BK=64) ----------------
// FIRST: gather(x16 rows via g_tok) @ w1^T -> swish -> g_h (fp16)
// else : g_h rows @ w2^T -> + b2 -> g_partial (fp32)
template <int K, bool FIRST>
__global__ __launch_bounds__(NT, 2) void gemm_kernel(const float* __restrict__ bias)
{
    const int e   = blockIdx.z;
    const int cnt = g_cnt[e];
    const int m0  = blockIdx.y * BM;
    if (m0 >= cnt) return;
    const int n0  = blockIdx.x * BN;
    constexpr int NTOT = FIRST ? H_ : D_;
    constexpr int NC = K / BK;

    extern __shared__ char smem_raw[];
    __shared__ int s_tok[BM];
    const uint32_t sbase = s2u(smem_raw);
    const int tid  = threadIdx.x;
    const int lane = tid & 31;
    const int wid  = tid >> 5;
    const int wm   = (wid & 1) * 64;   // warp m offset in tile
    const int wn   = (wid >> 1) * 32;  // warp n offset in tile

    if (FIRST) {
        if (tid < BM) {
            int m = m0 + tid;
            if (m >= cnt) m = cnt - 1;
            s_tok[tid] = g_tok[e * T_ + m];
        }
        __syncthreads();
    }

    const __half* A_g = FIRST ? g_x16 : (g_h + (size_t)(e * T_ + m0) * K);
    const __half* B_g = (FIRST ? g_w1 : g_w2) + ((size_t)e * NTOT + n0) * K;

    auto load_chunk = [&](int c, int s) {
        uint32_t stg = sbase + s * STAGE_B;
        #pragma unroll
        for (int q = 0; q < 8; q++) {
            int i   = tid + q * NT;       // 0..2047
            int mtx = i >> 10;            // 0 A, 1 B
            int rem = i & 1023;
            int r   = rem >> 3;
            int cc  = rem & 7;
            const __half* src;
            if (mtx == 0) {
                size_t rowoff = FIRST ? ((size_t)s_tok[r] * D_) : ((size_t)r * K);
                src = A_g + rowoff + c * BK + cc * 8;
            } else {
                src = B_g + (size_t)r * K + c * BK + cc * 8;
            }
            cpa16(stg + mtx * TILE_B + sw_off(r, cc), src);
        }
    };

    float acc[4][4][4] = {};

    // prologue: stage first STAGES-1 chunks
    #pragma unroll
    for (int c = 0; c < STAGES - 1; ++c) { load_chunk(c, c); cpa_commit(); }

    int s = 0;
    for (int c = 0; c < NC; ++c) {
        cpa_wait<STAGES - 2>();
        __syncthreads();
        const int cn = c + STAGES - 1;
        if (cn < NC) {
            int sn = s + STAGES - 1;
            if (sn >= STAGES) sn -= STAGES;
            load_chunk(cn, sn);
        }
        cpa_commit();

        const uint32_t sA = sbase + s * STAGE_B;
        const uint32_t sB = sA + TILE_B;

        #pragma unroll
        for (int ks = 0; ks < 4; ++ks) {
            uint32_t ah[4][4], bh[4][2];
            const int ar = lane & 15;
            const int ac = ks * 2 + (lane >> 4);
            #pragma unroll
            for (int im = 0; im < 4; im++) {
                uint32_t off = sw_off(wm + im * 16 + ar, ac);
                ldsm_x4(sA + off, ah[im][0], ah[im][1], ah[im][2], ah[im][3]);
            }
            // B: one ldmatrix.x4 covers 2 n-frags (16 rows) for this k16
            const int br = (lane & 7) + ((lane >> 4) << 3);
            const int bc = ks * 2 + ((lane >> 3) & 1);
            #pragma unroll
            for (int half = 0; half < 2; half++) {
                uint32_t off = sw_off(wn + half * 16 + br, bc);
                ldsm_x4(sB + off, bh[2 * half][0], bh[2 * half][1],
                                  bh[2 * half + 1][0], bh[2 * half + 1][1]);
            }
            #pragma unroll
            for (int im = 0; im < 4; im++)
                #pragma unroll
                for (int in = 0; in < 4; in++)
                    mma_f16(acc[im][in], ah[im], bh[in]);
        }
        if (++s == STAGES) s = 0;
    }

    // epilogue
    const int rbase = m0 + wm + (lane >> 2);
    #pragma unroll
    for (int im = 0; im < 4; im++) {
        #pragma unroll
        for (int half = 0; half < 2; half++) {
            const int mg = rbase + im * 16 + half * 8;
            if (mg >= cnt) continue;
            #pragma unroll
            for (int in = 0; in < 4; in++) {
                const int col = n0 + wn + in * 8 + 2 * (lane & 3);
                float z0 = acc[im][in][2 * half]     + bias[(size_t)e * NTOT + col];
                float z1 = acc[im][in][2 * half + 1] + bias[(size_t)e * NTOT + col + 1];
                if (FIRST) {
                    float w0 = z0 * __frcp_rn(1.f + __expf(-z0));
                    float w1 = z1 * __frcp_rn(1.f + __expf(-z1));
                    unsigned short h0 = __half_as_ushort(__float2half_rn(w0));
                    unsigned short h1 = __half_as_ushort(__float2half_rn(w1));
                    size_t o = ((size_t)(e * T_) + mg) * H_ + col;
                    *(uint32_t*)(g_h + o) = (uint32_t)h0 | ((uint32_t)h1 << 16);
                } else {
                    size_t o = ((size_t)(e * T_) + mg) * D_ + col;
                    *(float2*)(g_partial + o) = make_float2(z0, z1);
                }
            }
        }
    }
}

// out[t] = partial[a0] + partial[a1]
__global__ void sum_kernel(float* __restrict__ out) {
    int t = blockIdx.x;
    int a0 = g_assign[2 * t], a1 = g_assign[2 * t + 1];
    const float4* p0 = (const float4*)(g_partial + (size_t)a0 * D_);
    const float4* p1 = (const float4*)(g_partial + (size_t)a1 * D_);
    float4* o = (float4*)(out + (size_t)t * D_);
    int i = threadIdx.x;
    float4 u = p0[i], w = p1[i];
    o[i] = make_float4(u.x + w.x, u.y + w.y, u.z + w.z, u.w + w.w);
}

// ---------------- launch ----------------
extern "C" void kernel_launch(void* const* d_in, const int* in_sizes, int n_in,
                              void* d_out, int out_size)
{
    const float* x      = (const float*)d_in[0];
    const float* gate_v = (const float*)d_in[1];
    const float* gate_g = (const float*)d_in[2];
    const float* gate_b = (const float*)d_in[3];
    const float* w1_v   = (const float*)d_in[4];
    const float* w1_g   = (const float*)d_in[5];
    const float* b1     = (const float*)d_in[6];
    const float* w2_v   = (const float*)d_in[7];
    const float* w2_g   = (const float*)d_in[8];
    const float* b2     = (const float*)d_in[9];
    float* out = (float*)d_out;

    cudaFuncSetAttribute(gemm_kernel<D_, true>,  cudaFuncAttributeMaxDynamicSharedMemorySize, SMEM_DYN);
    cudaFuncSetAttribute(gemm_kernel<H_, false>, cudaFuncAttributeMaxDynamicSharedMemorySize, SMEM_DYN);

    init_kernel<<<1, 256>>>(gate_v, gate_g);
    prep_kernel<<<NB_PREP, 256>>>(x, gate_v, gate_b, w1_v, w1_g, w2_v, w2_g);

    gemm_kernel<D_, true><<<dim3(H_ / BN, T_ / BM, E_), NT, SMEM_DYN>>>(b1);
    gemm_kernel<H_, false><<<dim3(D_ / BN, T_ / BM, E_), NT, SMEM_DYN>>>(b2);

    sum_kernel<<<T_, 256>>>(out);
}

// round 10
// speedup vs baseline: 1.2891x; 1.0322x over previous
#include <cuda_runtime.h>
#include <cuda_fp16.h>
#include <math.h>
#include <stdint.h>

#define T_ 8192
#define D_ 1024
#define H_ 4096
#define E_ 8

#define BM 128
#define BN 128
#define BK 64
#define NT 256
#define STAGES 3
#define TILE_B (128 * 128)           // one 128x64 fp16 tile = 16384 bytes
#define STAGE_B (2 * TILE_B)         // A, B = 32768
#define SMEM_DYN (STAGES * STAGE_B)  // 98304

// prep kernel block ranges
#define NB_ROUTE 1024                // 8 tokens/block
#define NB_W1    4096                // 8 rows/block (E*H = 32768 rows, K=1024)
#define NB_W2    1024                // 8 rows/block (E*D = 8192 rows,  K=4096)
#define NB_PREP  (NB_ROUTE + NB_W1 + NB_W2)

// ---------------- static device scratch ----------------
__device__ float g_gs[E_];
__device__ int   g_cnt[E_];
__device__ int   g_tok[E_ * T_];          // expert slot -> token
__device__ int   g_assign[T_ * 2];        // token -> 2 assignment ids
__device__ __half g_xg[(size_t)E_ * T_ * D_];   // gathered x rows (fp16, duplicated)
__device__ __half g_w1[(size_t)E_ * H_ * D_];
__device__ __half g_w2[(size_t)E_ * D_ * H_];
__device__ __half g_h[(size_t)E_ * T_ * H_];

// ---------------- PTX helpers (generic sm_103-legal) ----------------
__device__ __forceinline__ uint32_t s2u(const void* p) {
    uint32_t a;
    asm("{ .reg .u64 t; cvta.to.shared.u64 t, %1; cvt.u32.u64 %0, t; }" : "=r"(a) : "l"(p));
    return a;
}
__device__ __forceinline__ void cpa16(uint32_t dst, const void* src) {
    asm volatile("cp.async.cg.shared.global [%0], [%1], 16;\n" :: "r"(dst), "l"(src) : "memory");
}
__device__ __forceinline__ void cpa_commit() { asm volatile("cp.async.commit_group;\n" ::: "memory"); }
template <int N> __device__ __forceinline__ void cpa_wait() {
    asm volatile("cp.async.wait_group %0;\n" :: "n"(N) : "memory");
}
__device__ __forceinline__ void ldsm_x4(uint32_t a, uint32_t& r0, uint32_t& r1, uint32_t& r2, uint32_t& r3) {
    asm volatile("ldmatrix.sync.aligned.m8n8.x4.shared.b16 {%0,%1,%2,%3}, [%4];"
                 : "=r"(r0), "=r"(r1), "=r"(r2), "=r"(r3) : "r"(a));
}
__device__ __forceinline__ void mma_f16(float* d, const uint32_t* a, const uint32_t* b) {
    asm volatile("mma.sync.aligned.m16n8k16.row.col.f32.f16.f16.f32 "
                 "{%0,%1,%2,%3}, {%4,%5,%6,%7}, {%8,%9}, {%0,%1,%2,%3};"
                 : "+f"(d[0]), "+f"(d[1]), "+f"(d[2]), "+f"(d[3])
                 : "r"(a[0]), "r"(a[1]), "r"(a[2]), "r"(a[3]), "r"(b[0]), "r"(b[1]));
}
// swizzled byte offset inside a Nx64 fp16 tile (rows of 128B, 16B chunks)
__device__ __forceinline__ uint32_t sw_off(int r, int c) {
    return (uint32_t)(r * 128 + ((c ^ (r & 7)) << 4));
}

// ---------------- init: zero counts + gate weight-norm scales ----------------
__global__ void init_kernel(const float* __restrict__ gv, const float* __restrict__ gg) {
    if (threadIdx.x < E_) g_cnt[threadIdx.x] = 0;
    int row = threadIdx.x >> 5;
    if (row >= E_) return;
    int lane = threadIdx.x & 31;
    const float4* p = (const float4*)(gv + (size_t)row * D_);
    float s = 0.f;
    for (int i = lane; i < D_ / 4; i += 32) {
        float4 a = p[i];
        s += a.x * a.x + a.y * a.y + a.z * a.z + a.w * a.w;
    }
    #pragma unroll
    for (int o = 16; o; o >>= 1) s += __shfl_xor_sync(0xffffffffu, s, o);
    if (lane == 0) g_gs[row] = gg[row] / fmaxf(sqrtf(s), 1e-12f);
}

// warp helper: weight-norm + fp16 quantize one row
__device__ __forceinline__ void wconv_row(const float* __restrict__ vrow, float gval,
                                          __half* __restrict__ orow, int K, int lane)
{
    const float4* p = (const float4*)vrow;
    float s = 0.f;
    int n4 = K >> 2;
    for (int i = lane; i < n4; i += 32) {
        float4 a = p[i];
        s += a.x * a.x + a.y * a.y + a.z * a.z + a.w * a.w;
    }
    #pragma unroll
    for (int o = 16; o; o >>= 1) s += __shfl_xor_sync(0xffffffffu, s, o);
    float scl = gval / fmaxf(sqrtf(s), 1e-12f);
    uint2* oh = (uint2*)orow;
    for (int i = lane; i < n4; i += 32) {
        float4 a = p[i];
        unsigned short h0 = __half_as_ushort(__float2half_rn(a.x * scl));
        unsigned short h1 = __half_as_ushort(__float2half_rn(a.y * scl));
        unsigned short h2 = __half_as_ushort(__float2half_rn(a.z * scl));
        unsigned short h3 = __half_as_ushort(__float2half_rn(a.w * scl));
        uint2 hp;
        hp.x = (uint32_t)h0 | ((uint32_t)h1 << 16);
        hp.y = (uint32_t)h2 | ((uint32_t)h3 << 16);
        oh[i] = hp;
    }
}

// ---------------- fused prep: route | wconv(w1) | wconv(w2) ----------------
__global__ __launch_bounds__(256) void prep_kernel(
    const float* __restrict__ x,
    const float* __restrict__ gate_v, const float* __restrict__ gate_b,
    const float* __restrict__ w1_v, const float* __restrict__ w1_g,
    const float* __restrict__ w2_v, const float* __restrict__ w2_g)
{
    const int b = blockIdx.x;
    const int tid = threadIdx.x;
    const int lane = tid & 31;
    const int warp = tid >> 5;

    if (b < NB_ROUTE) {
        // ---- routing: 1 warp per token, 8 tokens/block ----
        int t = b * 8 + warp;
        const float4* xp = (const float4*)(x + (size_t)t * D_);
        float4 xr[8];
        #pragma unroll
        for (int i = 0; i < 8; i++) xr[i] = xp[lane + 32 * i];
        float logit[E_];
        #pragma unroll
        for (int e = 0; e < E_; e++) {
            const float4* gp = (const float4*)(gate_v + (size_t)e * D_);
            float s = 0.f;
            #pragma unroll
            for (int i = 0; i < 8; i++) {
                float4 g4 = gp[lane + 32 * i];
                s += xr[i].x * g4.x + xr[i].y * g4.y + xr[i].z * g4.z + xr[i].w * g4.w;
            }
            #pragma unroll
            for (int o = 16; o; o >>= 1) s += __shfl_xor_sync(0xffffffffu, s, o);
            logit[e] = s;
        }
        if (lane == 0) {
            int b0 = -1, b1i = -1;
            float v0 = -1e30f, v1 = -1e30f;
            #pragma unroll
            for (int e = 0; e < E_; e++) {
                float l = logit[e] * g_gs[e] + gate_b[e];
                if (l > v0)      { v1 = v0; b1i = b0; v0 = l; b0 = e; }
                else if (l > v1) { v1 = l; b1i = e; }
            }
            int e0 = min(b0, b1i), e1 = max(b0, b1i);
            int s0 = atomicAdd(&g_cnt[e0], 1);
            g_tok[e0 * T_ + s0] = t;
            g_assign[2 * t] = e0 * T_ + s0;
            int s1 = atomicAdd(&g_cnt[e1], 1);
            g_tok[e1 * T_ + s1] = t;
            g_assign[2 * t + 1] = e1 * T_ + s1;
        }
    } else if (b < NB_ROUTE + NB_W1) {
        // ---- w1 weight-norm+convert: 8 rows/block, K = D_ ----
        int row = (b - NB_ROUTE) * 8 + warp;   // 0..E*H-1
        wconv_row(w1_v + (size_t)row * D_, w1_g[row], g_w1 + (size_t)row * D_, D_, lane);
    } else {
        // ---- w2 weight-norm+convert: 8 rows/block, K = H_ ----
        int row = (b - NB_ROUTE - NB_W1) * 8 + warp;   // 0..E*D-1
        wconv_row(w2_v + (size_t)row * H_, w2_g[row], g_w2 + (size_t)row * H_, H_, lane);
    }
}

// gather x rows into assignment slots as fp16 (duplicated per assignment)
__global__ void gather_kernel(const float* __restrict__ x) {
    int t = blockIdx.x;
    int i = threadIdx.x;   // 256 threads * float4 = 1024
    float4 v = ((const float4*)(x + (size_t)t * D_))[i];
    unsigned short h[4];
    h[0] = __half_as_ushort(__float2half_rn(v.x));
    h[1] = __half_as_ushort(__float2half_rn(v.y));
    h[2] = __half_as_ushort(__float2half_rn(v.z));
    h[3] = __half_as_ushort(__float2half_rn(v.w));
    uint2 hp;
    hp.x = (uint32_t)h[0] | ((uint32_t)h[1] << 16);
    hp.y = (uint32_t)h[2] | ((uint32_t)h[3] << 16);
    int a0 = g_assign[2 * t], a1 = g_assign[2 * t + 1];
    ((uint2*)(g_xg + (size_t)a0 * D_))[i] = hp;
    ((uint2*)(g_xg + (size_t)a1 * D_))[i] = hp;
}

// ---------------- fp16 HMMA GEMM (r6 config: CTA 128x128, 8 warps of 64x32, BK=64) ----------------
// FIRST: g_xg rows @ w1^T -> swish -> g_h (fp16)
// else : g_h rows @ w2^T -> + b2 -> atomicAdd into out (exactly 2 adds/elem, commutative)
template <int K, bool FIRST>
__global__ __launch_bounds__(NT, 2) void gemm_kernel(const float* __restrict__ bias,
                                                     float* __restrict__ out)
{
    const int e   = blockIdx.z;
    const int cnt = g_cnt[e];
    const int m0  = blockIdx.y * BM;
    if (m0 >= cnt) return;
    const int n0  = blockIdx.x * BN;
    constexpr int NTOT = FIRST ? H_ : D_;
    constexpr int NC = K / BK;

    extern __shared__ char smem_raw[];
    __shared__ int s_tok[BM];
    const uint32_t sbase = s2u(smem_raw);
    const int tid  = threadIdx.x;
    const int lane = tid & 31;
    const int wid  = tid >> 5;
    const int wm   = (wid & 1) * 64;   // warp m offset in tile
    const int wn   = (wid >> 1) * 32;  // warp n offset in tile

    if (!FIRST) {
        if (tid < BM) {
            int m = m0 + tid;
            if (m >= cnt) m = cnt - 1;
            s_tok[tid] = g_tok[e * T_ + m];
        }
        __syncthreads();
    }

    const size_t arow = (size_t)(e * T_ + m0);
    const __half* A_g = (FIRST ? g_xg : g_h) + arow * K;
    const __half* B_g = (FIRST ? g_w1 : g_w2) + ((size_t)e * NTOT + n0) * K;

    auto load_chunk = [&](int c, int s) {
        uint32_t stg = sbase + s * STAGE_B;
        #pragma unroll
        for (int q = 0; q < 8; q++) {
            int i   = tid + q * NT;       // 0..2047
            int mtx = i >> 10;            // 0 A, 1 B
            int rem = i & 1023;
            int r   = rem >> 3;
            int cc  = rem & 7;
            const __half* src = (mtx == 0) ? A_g : B_g;
            src += (size_t)r * K + c * BK + cc * 8;
            cpa16(stg + mtx * TILE_B + sw_off(r, cc), src);
        }
    };

    float acc[4][4][4] = {};

    // prologue: stage first STAGES-1 chunks
    #pragma unroll
    for (int c = 0; c < STAGES - 1; ++c) { load_chunk(c, c); cpa_commit(); }

    int s = 0;
    for (int c = 0; c < NC; ++c) {
        cpa_wait<STAGES - 2>();
        __syncthreads();
        const int cn = c + STAGES - 1;
        if (cn < NC) {
            int sn = s + STAGES - 1;
            if (sn >= STAGES) sn -= STAGES;
            load_chunk(cn, sn);
        }
        cpa_commit();

        const uint32_t sA = sbase + s * STAGE_B;
        const uint32_t sB = sA + TILE_B;

        #pragma unroll
        for (int ks = 0; ks < 4; ++ks) {
            uint32_t ah[4][4], bh[4][2];
            const int ar = lane & 15;
            const int ac = ks * 2 + (lane >> 4);
            #pragma unroll
            for (int im = 0; im < 4; im++) {
                uint32_t off = sw_off(wm + im * 16 + ar, ac);
                ldsm_x4(sA + off, ah[im][0], ah[im][1], ah[im][2], ah[im][3]);
            }
            // B: one ldmatrix.x4 covers 2 n-frags (16 rows) for this k16
            const int br = (lane & 7) + ((lane >> 4) << 3);
            const int bc = ks * 2 + ((lane >> 3) & 1);
            #pragma unroll
            for (int half = 0; half < 2; half++) {
                uint32_t off = sw_off(wn + half * 16 + br, bc);
                ldsm_x4(sB + off, bh[2 * half][0], bh[2 * half][1],
                                  bh[2 * half + 1][0], bh[2 * half + 1][1]);
            }
            #pragma unroll
            for (int im = 0; im < 4; im++)
                #pragma unroll
                for (int in = 0; in < 4; in++)
                    mma_f16(acc[im][in], ah[im], bh[in]);
        }
        if (++s == STAGES) s = 0;
    }

    // epilogue
    const int lrow = wm + (lane >> 2);
    #pragma unroll
    for (int im = 0; im < 4; im++) {
        #pragma unroll
        for (int half = 0; half < 2; half++) {
            const int lr = lrow + im * 16 + half * 8;
            const int mg = m0 + lr;
            if (mg >= cnt) continue;
            #pragma unroll
            for (int in = 0; in < 4; in++) {
                const int col = n0 + wn + in * 8 + 2 * (lane & 3);
                float z0 = acc[im][in][2 * half]     + bias[(size_t)e * NTOT + col];
                float z1 = acc[im][in][2 * half + 1] + bias[(size_t)e * NTOT + col + 1];
                if (FIRST) {
                    float w0 = z0 * __frcp_rn(1.f + __expf(-z0));
                    float w1 = z1 * __frcp_rn(1.f + __expf(-z1));
                    unsigned short h0 = __half_as_ushort(__float2half_rn(w0));
                    unsigned short h1 = __half_as_ushort(__float2half_rn(w1));
                    size_t o = ((size_t)(e * T_) + mg) * H_ + col;
                    *(uint32_t*)(g_h + o) = (uint32_t)h0 | ((uint32_t)h1 << 16);
                } else {
                    size_t o = (size_t)s_tok[lr] * D_ + col;
                    atomicAdd(out + o,     z0);
                    atomicAdd(out + o + 1, z1);
                }
            }
        }
    }
}

// ---------------- launch ----------------
extern "C" void kernel_launch(void* const* d_in, const int* in_sizes, int n_in,
                              void* d_out, int out_size)
{
    const float* x      = (const float*)d_in[0];
    const float* gate_v = (const float*)d_in[1];
    const float* gate_g = (const float*)d_in[2];
    const float* gate_b = (const float*)d_in[3];
    const float* w1_v   = (const float*)d_in[4];
    const float* w1_g   = (const float*)d_in[5];
    const float* b1     = (const float*)d_in[6];
    const float* w2_v   = (const float*)d_in[7];
    const float* w2_g   = (const float*)d_in[8];
    const float* b2     = (const float*)d_in[9];
    float* out = (float*)d_out;

    cudaFuncSetAttribute(gemm_kernel<D_, true>,  cudaFuncAttributeMaxDynamicSharedMemorySize, SMEM_DYN);
    cudaFuncSetAttribute(gemm_kernel<H_, false>, cudaFuncAttributeMaxDynamicSharedMemorySize, SMEM_DYN);

    init_kernel<<<1, 256>>>(gate_v, gate_g);
    cudaMemsetAsync(out, 0, (size_t)out_size * sizeof(float));
    prep_kernel<<<NB_PREP, 256>>>(x, gate_v, gate_b, w1_v, w1_g, w2_v, w2_g);
    gather_kernel<<<T_, 256>>>(x);

    gemm_kernel<D_, true><<<dim3(H_ / BN, T_ / BM, E_), NT, SMEM_DYN>>>(b1, out);
    gemm_kernel<H_, false><<<dim3(D_ / BN, T_ / BM, E_), NT, SMEM_DYN>>>(b2, out);
}

// round 11
// speedup vs baseline: 1.3219x; 1.0255x over previous
#include <cuda_runtime.h>
#include <cuda_fp16.h>
#include <math.h>
#include <stdint.h>

#define T_ 8192
#define D_ 1024
#define H_ 4096
#define E_ 8

#define BM 128
#define BN 128
#define BK 64
#define NT 256
#define STAGES 3
#define TILE_B (128 * 128)           // one 128x64 fp16 tile = 16384 bytes
#define STAGE_B (2 * TILE_B)         // A, B = 32768
#define SMEM_DYN (STAGES * STAGE_B)  // 98304

// prep kernel block ranges
#define NB_ROUTE 1024                // 8 tokens/block
#define NB_W1    4096                // 8 rows/block (E*H = 32768 rows, K=1024)
#define NB_W2    1024                // 8 rows/block (E*D = 8192 rows,  K=4096)
#define NB_PREP  (NB_ROUTE + NB_W1 + NB_W2)

// ---------------- static device scratch ----------------
__device__ float g_gs[E_];
__device__ int   g_cnt[E_];
__device__ int   g_tok[E_ * T_];          // expert slot -> token
__device__ int   g_assign[T_ * 2];        // token -> 2 assignment ids
__device__ __half g_xg[(size_t)E_ * T_ * D_];   // gathered x rows (fp16, duplicated)
__device__ __half g_w1[(size_t)E_ * H_ * D_];
__device__ __half g_w2[(size_t)E_ * D_ * H_];
__device__ __half g_h[(size_t)E_ * T_ * H_];

// ---------------- PTX helpers (generic sm_103-legal) ----------------
__device__ __forceinline__ uint32_t s2u(const void* p) {
    uint32_t a;
    asm("{ .reg .u64 t; cvta.to.shared.u64 t, %1; cvt.u32.u64 %0, t; }" : "=r"(a) : "l"(p));
    return a;
}
__device__ __forceinline__ void cpa16(uint32_t dst, const void* src) {
    asm volatile("cp.async.cg.shared.global [%0], [%1], 16;\n" :: "r"(dst), "l"(src) : "memory");
}
__device__ __forceinline__ void cpa_commit() { asm volatile("cp.async.commit_group;\n" ::: "memory"); }
template <int N> __device__ __forceinline__ void cpa_wait() {
    asm volatile("cp.async.wait_group %0;\n" :: "n"(N) : "memory");
}
__device__ __forceinline__ void ldsm_x4(uint32_t a, uint32_t& r0, uint32_t& r1, uint32_t& r2, uint32_t& r3) {
    asm volatile("ldmatrix.sync.aligned.m8n8.x4.shared.b16 {%0,%1,%2,%3}, [%4];"
                 : "=r"(r0), "=r"(r1), "=r"(r2), "=r"(r3) : "r"(a));
}
__device__ __forceinline__ void mma_f16(float* d, const uint32_t* a, const uint32_t* b) {
    asm volatile("mma.sync.aligned.m16n8k16.row.col.f32.f16.f16.f32 "
                 "{%0,%1,%2,%3}, {%4,%5,%6,%7}, {%8,%9}, {%0,%1,%2,%3};"
                 : "+f"(d[0]), "+f"(d[1]), "+f"(d[2]), "+f"(d[3])
                 : "r"(a[0]), "r"(a[1]), "r"(a[2]), "r"(a[3]), "r"(b[0]), "r"(b[1]));
}
__device__ __forceinline__ float rcp_approx(float x) {
    float r;
    asm("rcp.approx.f32 %0, %1;" : "=f"(r) : "f"(x));
    return r;
}
// swizzled byte offset inside a Nx64 fp16 tile (rows of 128B, 16B chunks)
__device__ __forceinline__ uint32_t sw_off(int r, int c) {
    return (uint32_t)(r * 128 + ((c ^ (r & 7)) << 4));
}

// ---------------- init: zero counts + gate weight-norm scales ----------------
__global__ void init_kernel(const float* __restrict__ gv, const float* __restrict__ gg) {
    if (threadIdx.x < E_) g_cnt[threadIdx.x] = 0;
    int row = threadIdx.x >> 5;
    if (row >= E_) return;
    int lane = threadIdx.x & 31;
    const float4* p = (const float4*)(gv + (size_t)row * D_);
    float s = 0.f;
    for (int i = lane; i < D_ / 4; i += 32) {
        float4 a = p[i];
        s += a.x * a.x + a.y * a.y + a.z * a.z + a.w * a.w;
    }
    #pragma unroll
    for (int o = 16; o; o >>= 1) s += __shfl_xor_sync(0xffffffffu, s, o);
    if (lane == 0) g_gs[row] = gg[row] / fmaxf(sqrtf(s), 1e-12f);
}

// warp helper: weight-norm + fp16 quantize one row
__device__ __forceinline__ void wconv_row(const float* __restrict__ vrow, float gval,
                                          __half* __restrict__ orow, int K, int lane)
{
    const float4* p = (const float4*)vrow;
    float s = 0.f;
    int n4 = K >> 2;
    for (int i = lane; i < n4; i += 32) {
        float4 a = p[i];
        s += a.x * a.x + a.y * a.y + a.z * a.z + a.w * a.w;
    }
    #pragma unroll
    for (int o = 16; o; o >>= 1) s += __shfl_xor_sync(0xffffffffu, s, o);
    float scl = gval / fmaxf(sqrtf(s), 1e-12f);
    uint2* oh = (uint2*)orow;
    for (int i = lane; i < n4; i += 32) {
        float4 a = p[i];
        unsigned short h0 = __half_as_ushort(__float2half_rn(a.x * scl));
        unsigned short h1 = __half_as_ushort(__float2half_rn(a.y * scl));
        unsigned short h2 = __half_as_ushort(__float2half_rn(a.z * scl));
        unsigned short h3 = __half_as_ushort(__float2half_rn(a.w * scl));
        uint2 hp;
        hp.x = (uint32_t)h0 | ((uint32_t)h1 << 16);
        hp.y = (uint32_t)h2 | ((uint32_t)h3 << 16);
        oh[i] = hp;
    }
}

// ---------------- fused prep: route | wconv(w1) | wconv(w2) ----------------
__global__ __launch_bounds__(256) void prep_kernel(
    const float* __restrict__ x,
    const float* __restrict__ gate_v, const float* __restrict__ gate_b,
    const float* __restrict__ w1_v, const float* __restrict__ w1_g,
    const float* __restrict__ w2_v, const float* __restrict__ w2_g)
{
    const int b = blockIdx.x;
    const int tid = threadIdx.x;
    const int lane = tid & 31;
    const int warp = tid >> 5;

    if (b < NB_ROUTE) {
        // ---- routing: 1 warp per token, 8 tokens/block ----
        int t = b * 8 + warp;
        const float4* xp = (const float4*)(x + (size_t)t * D_);
        float4 xr[8];
        #pragma unroll
        for (int i = 0; i < 8; i++) xr[i] = xp[lane + 32 * i];
        float logit[E_];
        #pragma unroll
        for (int e = 0; e < E_; e++) {
            const float4* gp = (const float4*)(gate_v + (size_t)e * D_);
            float s = 0.f;
            #pragma unroll
            for (int i = 0; i < 8; i++) {
                float4 g4 = gp[lane + 32 * i];
                s += xr[i].x * g4.x + xr[i].y * g4.y + xr[i].z * g4.z + xr[i].w * g4.w;
            }
            #pragma unroll
            for (int o = 16; o; o >>= 1) s += __shfl_xor_sync(0xffffffffu, s, o);
            logit[e] = s;
        }
        if (lane == 0) {
            int b0 = -1, b1i = -1;
            float v0 = -1e30f, v1 = -1e30f;
            #pragma unroll
            for (int e = 0; e < E_; e++) {
                float l = logit[e] * g_gs[e] + gate_b[e];
                if (l > v0)      { v1 = v0; b1i = b0; v0 = l; b0 = e; }
                else if (l > v1) { v1 = l; b1i = e; }
            }
            int e0 = min(b0, b1i), e1 = max(b0, b1i);
            int s0 = atomicAdd(&g_cnt[e0], 1);
            g_tok[e0 * T_ + s0] = t;
            g_assign[2 * t] = e0 * T_ + s0;
            int s1 = atomicAdd(&g_cnt[e1], 1);
            g_tok[e1 * T_ + s1] = t;
            g_assign[2 * t + 1] = e1 * T_ + s1;
        }
    } else if (b < NB_ROUTE + NB_W1) {
        // ---- w1 weight-norm+convert: 8 rows/block, K = D_ ----
        int row = (b - NB_ROUTE) * 8 + warp;   // 0..E*H-1
        wconv_row(w1_v + (size_t)row * D_, w1_g[row], g_w1 + (size_t)row * D_, D_, lane);
    } else {
        // ---- w2 weight-norm+convert: 8 rows/block, K = H_ ----
        int row = (b - NB_ROUTE - NB_W1) * 8 + warp;   // 0..E*D-1
        wconv_row(w2_v + (size_t)row * H_, w2_g[row], g_w2 + (size_t)row * H_, H_, lane);
    }
}

// gather x rows into assignment slots as fp16 (duplicated per assignment)
__global__ void gather_kernel(const float* __restrict__ x) {
    int t = blockIdx.x;
    int i = threadIdx.x;   // 256 threads * float4 = 1024
    float4 v = ((const float4*)(x + (size_t)t * D_))[i];
    unsigned short h[4];
    h[0] = __half_as_ushort(__float2half_rn(v.x));
    h[1] = __half_as_ushort(__float2half_rn(v.y));
    h[2] = __half_as_ushort(__float2half_rn(v.z));
    h[3] = __half_as_ushort(__float2half_rn(v.w));
    uint2 hp;
    hp.x = (uint32_t)h[0] | ((uint32_t)h[1] << 16);
    hp.y = (uint32_t)h[2] | ((uint32_t)h[3] << 16);
    int a0 = g_assign[2 * t], a1 = g_assign[2 * t + 1];
    ((uint2*)(g_xg + (size_t)a0 * D_))[i] = hp;
    ((uint2*)(g_xg + (size_t)a1 * D_))[i] = hp;
}

// ---------------- fp16 HMMA GEMM (CTA 128x128, 8 warps of 64x32, BK=64) ----------------
// FIRST: g_xg rows @ w1^T -> swish -> g_h (fp16)
// else : g_h rows @ w2^T -> + b2 -> atomicAdd into out (exactly 2 adds/elem, commutative)
template <int K, bool FIRST>
__global__ __launch_bounds__(NT, 2) void gemm_kernel(const float* __restrict__ bias,
                                                     float* __restrict__ out)
{
    const int e   = blockIdx.z;
    const int cnt = g_cnt[e];
    const int m0  = blockIdx.y * BM;
    if (m0 >= cnt) return;
    const int n0  = blockIdx.x * BN;
    constexpr int NTOT = FIRST ? H_ : D_;
    constexpr int NC = K / BK;

    extern __shared__ char smem_raw[];
    __shared__ int s_tok[BM];
    const uint32_t sbase = s2u(smem_raw);
    const int tid  = threadIdx.x;
    const int lane = tid & 31;
    const int wid  = tid >> 5;
    const int wm   = (wid & 1) * 64;   // warp m offset in tile
    const int wn   = (wid >> 1) * 32;  // warp n offset in tile

    if (!FIRST) {
        if (tid < BM) {
            int m = m0 + tid;
            if (m >= cnt) m = cnt - 1;
            s_tok[tid] = g_tok[e * T_ + m];
        }
        __syncthreads();
    }

    const size_t arow = (size_t)(e * T_ + m0);
    const __half* A_g = (FIRST ? g_xg : g_h) + arow * K;
    const __half* B_g = (FIRST ? g_w1 : g_w2) + ((size_t)e * NTOT + n0) * K;

    auto load_chunk = [&](int c, int s) {
        uint32_t stg = sbase + s * STAGE_B;
        #pragma unroll
        for (int q = 0; q < 8; q++) {
            int i   = tid + q * NT;       // 0..2047
            int mtx = i >> 10;            // 0 A, 1 B
            int rem = i & 1023;
            int r   = rem >> 3;
            int cc  = rem & 7;
            const __half* src = (mtx == 0) ? A_g : B_g;
            src += (size_t)r * K + c * BK + cc * 8;
            cpa16(stg + mtx * TILE_B + sw_off(r, cc), src);
        }
    };

    float acc[4][4][4] = {};

    // prologue: stage first STAGES-1 chunks
    #pragma unroll
    for (int c = 0; c < STAGES - 1; ++c) { load_chunk(c, c); cpa_commit(); }

    int s = 0;
    for (int c = 0; c < NC; ++c) {
        cpa_wait<STAGES - 2>();
        __syncthreads();
        const int cn = c + STAGES - 1;
        if (cn < NC) {
            int sn = s + STAGES - 1;
            if (sn >= STAGES) sn -= STAGES;
            load_chunk(cn, sn);
        }
        cpa_commit();

        const uint32_t sA = sbase + s * STAGE_B;
        const uint32_t sB = sA + TILE_B;

        #pragma unroll
        for (int ks = 0; ks < 4; ++ks) {
            uint32_t ah[4][4], bh[4][2];
            const int ar = lane & 15;
            const int ac = ks * 2 + (lane >> 4);
            #pragma unroll
            for (int im = 0; im < 4; im++) {
                uint32_t off = sw_off(wm + im * 16 + ar, ac);
                ldsm_x4(sA + off, ah[im][0], ah[im][1], ah[im][2], ah[im][3]);
            }
            // B: one ldmatrix.x4 covers 2 n-frags (16 rows) for this k16
            const int br = (lane & 7) + ((lane >> 4) << 3);
            const int bc = ks * 2 + ((lane >> 3) & 1);
            #pragma unroll
            for (int half = 0; half < 2; half++) {
                uint32_t off = sw_off(wn + half * 16 + br, bc);
                ldsm_x4(sB + off, bh[2 * half][0], bh[2 * half][1],
                                  bh[2 * half + 1][0], bh[2 * half + 1][1]);
            }
            #pragma unroll
            for (int im = 0; im < 4; im++)
                #pragma unroll
                for (int in = 0; in < 4; in++)
                    mma_f16(acc[im][in], ah[im], bh[in]);
        }
        if (++s == STAGES) s = 0;
    }

    // epilogue: hoist the 8 distinct bias values per thread into registers
    float bs0[4], bs1[4];
    #pragma unroll
    for (int in = 0; in < 4; in++) {
        const int col = n0 + wn + in * 8 + 2 * (lane & 3);
        bs0[in] = bias[(size_t)e * NTOT + col];
        bs1[in] = bias[(size_t)e * NTOT + col + 1];
    }
    const int lrow = wm + (lane >> 2);
    #pragma unroll
    for (int im = 0; im < 4; im++) {
        #pragma unroll
        for (int half = 0; half < 2; half++) {
            const int lr = lrow + im * 16 + half * 8;
            const int mg = m0 + lr;
            if (mg >= cnt) continue;
            #pragma unroll
            for (int in = 0; in < 4; in++) {
                const int col = n0 + wn + in * 8 + 2 * (lane & 3);
                float z0 = acc[im][in][2 * half]     + bs0[in];
                float z1 = acc[im][in][2 * half + 1] + bs1[in];
                if (FIRST) {
                    float w0 = z0 * rcp_approx(1.f + __expf(-z0));
                    float w1 = z1 * rcp_approx(1.f + __expf(-z1));
                    unsigned short h0 = __half_as_ushort(__float2half_rn(w0));
                    unsigned short h1 = __half_as_ushort(__float2half_rn(w1));
                    size_t o = ((size_t)(e * T_) + mg) * H_ + col;
                    *(uint32_t*)(g_h + o) = (uint32_t)h0 | ((uint32_t)h1 << 16);
                } else {
                    size_t o = (size_t)s_tok[lr] * D_ + col;
                    atomicAdd(out + o,     z0);
                    atomicAdd(out + o + 1, z1);
                }
            }
        }
    }
}

// ---------------- launch ----------------
extern "C" void kernel_launch(void* const* d_in, const int* in_sizes, int n_in,
                              void* d_out, int out_size)
{
    const float* x      = (const float*)d_in[0];
    const float* gate_v = (const float*)d_in[1];
    const float* gate_g = (const float*)d_in[2];
    const float* gate_b = (const float*)d_in[3];
    const float* w1_v   = (const float*)d_in[4];
    const float* w1_g   = (const float*)d_in[5];
    const float* b1     = (const float*)d_in[6];
    const float* w2_v   = (const float*)d_in[7];
    const float* w2_g   = (const float*)d_in[8];
    const float* b2     = (const float*)d_in[9];
    float* out = (float*)d_out;

    cudaFuncSetAttribute(gemm_kernel<D_, true>,  cudaFuncAttributeMaxDynamicSharedMemorySize, SMEM_DYN);
    cudaFuncSetAttribute(gemm_kernel<H_, false>, cudaFuncAttributeMaxDynamicSharedMemorySize, SMEM_DYN);

    init_kernel<<<1, 256>>>(gate_v, gate_g);
    cudaMemsetAsync(out, 0, (size_t)out_size * sizeof(float));
    prep_kernel<<<NB_PREP, 256>>>(x, gate_v, gate_b, w1_v, w1_g, w2_v, w2_g);
    gather_kernel<<<T_, 256>>>(x);

    gemm_kernel<D_, true><<<dim3(H_ / BN, T_ / BM, E_), NT, SMEM_DYN>>>(b1, out);
    gemm_kernel<H_, false><<<dim3(D_ / BN, T_ / BM, E_), NT, SMEM_DYN>>>(b2, out);
}